// round 7
// baseline (speedup 1.0000x reference)
#include <cuda_runtime.h>

#define BB   32
#define NN   1024
#define DDIM 256
#define NCAP 32
#define DCAP 64

typedef unsigned long long u64;

__device__ __forceinline__ void fma2(u64& d, u64 a, u64 b){
    asm("fma.rn.f32x2 %0, %1, %2, %0;" : "+l"(d) : "l"(a), "l"(b));
}
__device__ __forceinline__ float2 unpk(u64 v){
    float2 r; asm("mov.b64 {%0,%1}, %2;" : "=f"(r.x), "=f"(r.y) : "l"(v)); return r;
}
__device__ __forceinline__ float sum2(u64 v){ float2 r = unpk(v); return r.x + r.y; }

#define NJC 16   // j-chunks for k_x / k_bupd

// ---- scratch ----
__device__ __align__(16) float g_xpart[BB*8*DDIM];         // mean partials
__device__ __align__(16) float g_b[BB*NCAP*NN];            // routing logits
__device__ __align__(16) float g_sum[BB*NCAP];             // softmax sum-exp (no-max)
__device__ __align__(16) float g_xp[NJC*BB*NCAP*DDIM];     // x partials per j-chunk
__device__ __align__(16) float g_wv[BB*NCAP*DDIM];         // W_i @ v

// ---------------------------------------------------------------------------
// K1: partial mean of u over j. grid (32 b, 8 p), 256 threads.
// ---------------------------------------------------------------------------
__global__ void k_meanpart(const float* __restrict__ u){
    int b = blockIdx.x, p = blockIdx.y, d = threadIdx.x;
    const float* up = u + ((size_t)b*NN + p*128)*DDIM + d;
    float acc = 0.f;
    #pragma unroll 8
    for (int j = 0; j < 128; ++j) acc += up[(size_t)j*DDIM];
    g_xpart[(b*8+p)*DDIM + d] = acc;
}

// ---------------------------------------------------------------------------
// K2: per (i, 8-batch group): s = x@W_i ; v = squash(s) ; w_v = W_i@v.
// grid (32 i, 4 bq), 256 threads. MODE 0: x from mean partials.
// MODE 1: x = sum of NJC g_xp partials. MODE 2: like 1 but write v to out.
// ---------------------------------------------------------------------------
template<int MODE>
__global__ void k_sv(const float* __restrict__ W, float* __restrict__ out){
    int i = blockIdx.x, bq = blockIdx.y;
    int t = threadIdx.x;
    extern __shared__ float Wt_s[];          // [256][66]
    __shared__ float2 xsD[8][DDIM];
    __shared__ float  sm[8][DCAP];
    __shared__ float  vs[8][DCAP];

    if (MODE != 2 && t < 8) g_sum[(bq*8+t)*NCAP + i] = 0.f;

    #pragma unroll 4
    for (int p = 0; p < 16; ++p){
        int idx = t + 256*p;
        int d = idx >> 4, m4 = idx & 15;
        float4 w4 = *(const float4*)(W + (size_t)d*2048 + i*64 + m4*4);
        float* wp = &Wt_s[d*66 + m4*4];
        wp[0]=w4.x; wp[1]=w4.y; wp[2]=w4.z; wp[3]=w4.w;
    }
    #pragma unroll
    for (int p = 0; p < 8; ++p){
        int idx = t + 256*p;
        int bb = idx >> 8, d = idx & 255;
        float a;
        if (MODE == 0){
            a = 0.f;
            #pragma unroll
            for (int q = 0; q < 8; ++q) a += g_xpart[(((bq*8+bb)*8)+q)*DDIM + d];
            a *= (1.0f/1024.0f);
        } else {
            size_t bi = (((size_t)(bq*8+bb))*NCAP + i)*DDIM + d;
            a = 0.f;
            #pragma unroll
            for (int q = 0; q < NJC; ++q) a += g_xp[(size_t)q*BB*NCAP*DDIM + bi];
        }
        xsD[bb][d] = make_float2(a, a);
    }
    __syncthreads();

    {
        int mp = t & 31, bb = t >> 5;
        u64 acc = 0ull;
        const u64* xrow = (const u64*)&xsD[bb][0];
        #pragma unroll 8
        for (int d = 0; d < DDIM; ++d){
            u64 w2 = *(const u64*)&Wt_s[d*66 + 2*mp];
            fma2(acc, w2, xrow[d]);
        }
        float2 sp = unpk(acc);
        sm[bb][2*mp] = sp.x; sm[bb][2*mp+1] = sp.y;
    }
    __syncthreads();

    {
        int w = t >> 5, lane = t & 31;
        float s0 = sm[w][lane], s1 = sm[w][lane+32];
        float q = s0*s0 + s1*s1;
        #pragma unroll
        for (int o = 16; o; o >>= 1) q += __shfl_xor_sync(0xffffffffu, q, o);
        float r = rsqrtf(q + 1e-7f);
        if (MODE == 2){
            size_t ob = ((size_t)(bq*8+w)*NCAP + i)*DCAP;
            out[ob + lane]      = s0*r;
            out[ob + lane + 32] = s1*r;
            return;
        }
        vs[w][lane] = s0*r; vs[w][lane+32] = s1*r;
    }
    __syncthreads();

    {
        float wv[8] = {0,0,0,0,0,0,0,0};
        #pragma unroll 8
        for (int m = 0; m < DCAP; ++m){
            float wtv = Wt_s[t*66 + m];
            #pragma unroll
            for (int b8 = 0; b8 < 8; ++b8) wv[b8] = fmaf(wtv, vs[b8][m], wv[b8]);
        }
        #pragma unroll
        for (int b8 = 0; b8 < 8; ++b8)
            g_wv[(((size_t)(bq*8+b8))*NCAP + i)*DDIM + t] = wv[b8];
    }
}

// ---------------------------------------------------------------------------
// K3: b[b,i,j] (+)= sum_d u[b,j,d]*wv[b,i,d]; epilogue: sum-of-exp per i.
// d-paired f32x2, no operand duplication. grid (32 b, 16 jc), 256 thr.
// Block: 64 j x 32 i, reduce d=256. Thread tile 2j x 4i.
// dyn smem: wvS[32][260] + Us[64][68] + red[256].
// ---------------------------------------------------------------------------
#define BUP_US_ROW 68
#define BUP_WV_ROW 260
template<bool ACC>
__global__ void __launch_bounds__(256) k_bupd(const float* __restrict__ u){
    int b = blockIdx.x, jb = blockIdx.y*64;
    int t = threadIdx.x;
    int ig = t & 7, jg = t >> 3;                 // ig: 4 i, jg: 2 j
    extern __shared__ float smem_[];
    float* wvS = smem_;                          // [32][260]
    float* Us  = smem_ + 32*BUP_WV_ROW;          // [64][68]
    float* red = Us + 64*BUP_US_ROW;             // [8][32]

    // stage wv (32 i x 256 d), un-duplicated
    #pragma unroll
    for (int p = 0; p < 8; ++p){
        int lin = t + 256*p;                     // 2048 float4
        int i = lin >> 6, f4 = lin & 63;
        float4 w4 = *(const float4*)(g_wv + ((size_t)b*NCAP + i)*DDIM + f4*4);
        *(float4*)&wvS[i*BUP_WV_ROW + f4*4] = w4;
    }

    u64 acc[2][4];
    #pragma unroll
    for (int p = 0; p < 2; ++p)
        #pragma unroll
        for (int q = 0; q < 4; ++q) acc[p][q] = 0ull;

    for (int dt = 0; dt < DDIM; dt += 64){
        __syncthreads();                          // also covers wvS staging (1st iter)
        #pragma unroll
        for (int p = 0; p < 4; ++p){
            int lin = t + 256*p;                 // 1024 float4 (64j x 64d)
            int j = lin >> 4, f4 = lin & 15;
            float4 v4 = *(const float4*)(u + ((size_t)b*NN + jb + j)*DDIM + dt + f4*4);
            *(float4*)&Us[j*BUP_US_ROW + f4*4] = v4;
        }
        __syncthreads();
        #pragma unroll
        for (int s = 0; s < 16; ++s){            // 4 d (2 pairs) per step
            ulonglong2 A0 = *(const ulonglong2*)&Us[(jg*2+0)*BUP_US_ROW + s*4];
            ulonglong2 A1 = *(const ulonglong2*)&Us[(jg*2+1)*BUP_US_ROW + s*4];
            #pragma unroll
            for (int q = 0; q < 4; ++q){
                ulonglong2 Wv = *(const ulonglong2*)&wvS[(ig*4+q)*BUP_WV_ROW + dt + s*4];
                fma2(acc[0][q], A0.x, Wv.x); fma2(acc[0][q], A0.y, Wv.y);
                fma2(acc[1][q], A1.x, Wv.x); fma2(acc[1][q], A1.y, Wv.y);
            }
        }
    }

    // epilogue: b store (2 consecutive j per thread) + exp-sum per i
    float es[4];
    #pragma unroll
    for (int q = 0; q < 4; ++q){
        int i = ig*4 + q;
        float2 r = make_float2(sum2(acc[0][q]), sum2(acc[1][q]));
        float2* bp = (float2*)(g_b + ((size_t)b*NCAP + i)*NN + jb + jg*2);
        if (ACC){
            float2 o = *bp;
            r.x += o.x; r.y += o.y;
        }
        *bp = r;
        es[q] = __expf(r.x) + __expf(r.y);
    }
    // reduce over jg within warp (lanes share ig pattern: l and l+8,16,24)
    #pragma unroll
    for (int q = 0; q < 4; ++q){
        es[q] += __shfl_down_sync(0xffffffffu, es[q], 16);
        es[q] += __shfl_down_sync(0xffffffffu, es[q], 8);
    }
    int w = t >> 5, lane = t & 31;
    if (lane < 8){
        #pragma unroll
        for (int q = 0; q < 4; ++q) red[w*32 + lane*4 + q] = es[q];
    }
    __syncthreads();
    if (t < 32){
        float s = 0.f;
        #pragma unroll
        for (int ww = 0; ww < 8; ++ww) s += red[ww*32 + t];
        atomicAdd(&g_sum[b*NCAP + t], s);
    }
}

// ---------------------------------------------------------------------------
// K4: x partial: g_xp[jc][b,i,d] = sum_{j in chunk} c_ij * u[j,d].
// grid (32 b, 16 jc), 256 thr (8 warps). Block: 64 j, all 256 d, all 32 i.
// Thread: dg = lane (4 d-pairs), ig = warp (4 i). C loads are warp-broadcast.
// ---------------------------------------------------------------------------
__global__ void __launch_bounds__(256) k_x(const float* __restrict__ u){
    int b = blockIdx.x, jc = blockIdx.y;
    int t = threadIdx.x;
    int dg = t & 31, ig = t >> 5;                // dg: 4 d-pairs, ig: 4 i
    __shared__ float  Us[16*264];                // [j][256 d] pad 264
    __shared__ float2 CsD[16*34];                // [j][32 i] duplicated
    __shared__ float  inv[NCAP];
    if (t < 32) inv[t] = 1.0f / g_sum[b*NCAP + t];
    __syncthreads();

    u64 acc[4][4];
    #pragma unroll
    for (int p = 0; p < 4; ++p)
        #pragma unroll
        for (int q = 0; q < 4; ++q) acc[p][q] = 0ull;

    int j0 = jc*64;
    for (int jt = 0; jt < 64; jt += 16){
        // stage Us: 16j x 256d = 1024 float4
        #pragma unroll
        for (int p = 0; p < 4; ++p){
            int lin = t + 256*p;
            int j = lin >> 6, f4 = lin & 63;
            float4 v4 = *(const float4*)(u + ((size_t)b*NN + j0 + jt + j)*DDIM + f4*4);
            *(float4*)&Us[j*264 + f4*4] = v4;
        }
        // stage c: 16j x 32i
        #pragma unroll
        for (int p = 0; p < 2; ++p){
            int lin = t + 256*p;
            int i = lin >> 4, jj = lin & 15;
            float bv = g_b[((size_t)b*NCAP + i)*NN + j0 + jt + jj];
            float c = __expf(bv) * inv[i];
            CsD[jj*34 + i] = make_float2(c, c);
        }
        __syncthreads();
        #pragma unroll
        for (int jj = 0; jj < 16; ++jj){
            ulonglong2 A0 = *(const ulonglong2*)&Us[jj*264 + dg*8];
            ulonglong2 A1 = *(const ulonglong2*)&Us[jj*264 + dg*8 + 4];
            ulonglong2 C0 = *(const ulonglong2*)&CsD[jj*34 + ig*4];
            ulonglong2 C1 = *(const ulonglong2*)&CsD[jj*34 + ig*4 + 2];
            u64 a[4] = {A0.x, A0.y, A1.x, A1.y};
            u64 c[4] = {C0.x, C0.y, C1.x, C1.y};
            #pragma unroll
            for (int p = 0; p < 4; ++p)
                #pragma unroll
                for (int q = 0; q < 4; ++q)
                    fma2(acc[p][q], a[p], c[q]);
        }
        __syncthreads();
    }
    // write partials: d floats at dg*8 .. dg*8+7
    #pragma unroll
    for (int q = 0; q < 4; ++q){
        int i = ig*4 + q;
        float2 r0 = unpk(acc[0][q]), r1 = unpk(acc[1][q]);
        float2 r2 = unpk(acc[2][q]), r3 = unpk(acc[3][q]);
        float* xp = g_xp + (size_t)jc*BB*NCAP*DDIM
                  + ((size_t)b*NCAP + i)*DDIM + dg*8;
        *(float4*)xp       = make_float4(r0.x, r0.y, r1.x, r1.y);
        *(float4*)(xp + 4) = make_float4(r2.x, r2.y, r3.x, r3.y);
    }
}

// ---------------------------------------------------------------------------
extern "C" void kernel_launch(void* const* d_in, const int* in_sizes, int n_in,
                              void* d_out, int out_size){
    const float* u = (const float*)d_in[0];
    const float* W = (const float*)d_in[1];
    if (n_in >= 2 && in_sizes[0] < in_sizes[1]){
        u = (const float*)d_in[1];
        W = (const float*)d_in[0];
    }
    float* out = (float*)d_out;

    const int SV_SMEM  = 256*66*sizeof(float);                              // 67584
    const int BUP_SMEM = (32*BUP_WV_ROW + 64*BUP_US_ROW + 256)*sizeof(float); // ~52 KB
    static bool attr_done = false;
    if (!attr_done){
        cudaFuncSetAttribute(k_sv<0>,       cudaFuncAttributeMaxDynamicSharedMemorySize, SV_SMEM);
        cudaFuncSetAttribute(k_sv<1>,       cudaFuncAttributeMaxDynamicSharedMemorySize, SV_SMEM);
        cudaFuncSetAttribute(k_sv<2>,       cudaFuncAttributeMaxDynamicSharedMemorySize, SV_SMEM);
        cudaFuncSetAttribute(k_bupd<false>, cudaFuncAttributeMaxDynamicSharedMemorySize, BUP_SMEM);
        cudaFuncSetAttribute(k_bupd<true>,  cudaFuncAttributeMaxDynamicSharedMemorySize, BUP_SMEM);
        attr_done = true;
    }

    // iter 0 (softmax of zeros == mean)
    k_meanpart   <<<dim3(32,8),   256>>>(u);
    k_sv<0>      <<<dim3(32,4),   256, SV_SMEM>>>(W, out);
    k_bupd<false><<<dim3(32,NJC), 256, BUP_SMEM>>>(u);
    // iter 1
    k_x          <<<dim3(32,NJC), 256>>>(u);
    k_sv<1>      <<<dim3(32,4),   256, SV_SMEM>>>(W, out);
    k_bupd<true> <<<dim3(32,NJC), 256, BUP_SMEM>>>(u);
    // iter 2 (final)
    k_x          <<<dim3(32,NJC), 256>>>(u);
    k_sv<2>      <<<dim3(32,4),   256, SV_SMEM>>>(W, out);
}

// round 8
// speedup vs baseline: 1.6009x; 1.6009x over previous
#include <cuda_runtime.h>

#define BB   32
#define NN   1024
#define DDIM 256
#define NCAP 32
#define DCAP 64

typedef unsigned long long u64;

__device__ __forceinline__ void fma2(u64& d, u64 a, u64 b){
    asm("fma.rn.f32x2 %0, %1, %2, %0;" : "+l"(d) : "l"(a), "l"(b));
}
__device__ __forceinline__ float2 unpk(u64 v){
    float2 r; asm("mov.b64 {%0,%1}, %2;" : "=f"(r.x), "=f"(r.y) : "l"(v)); return r;
}
__device__ __forceinline__ float sum2(u64 v){ float2 r = unpk(v); return r.x + r.y; }

#define NJC 8   // j-chunks for k_x partials

// ---- scratch ----
__device__ __align__(16) float g_xpart[BB*8*DDIM];       // mean partials
__device__ __align__(16) float g_b[BB*NCAP*NN];          // routing logits
__device__ __align__(16) float g_sum[BB*NCAP];           // softmax sum-exp (no-max)
__device__ __align__(16) float g_xp[NJC*BB*NCAP*DDIM];   // x partials (8 j-chunks)
__device__ __align__(16) float g_wv[BB*NCAP*DDIM];       // W_i @ v

// ---------------------------------------------------------------------------
// K1: partial mean of u over j. grid (32 b, 8 p), 256 threads.
// ---------------------------------------------------------------------------
__global__ void k_meanpart(const float* __restrict__ u){
    int b = blockIdx.x, p = blockIdx.y, d = threadIdx.x;
    const float* up = u + ((size_t)b*NN + p*128)*DDIM + d;
    float acc = 0.f;
    #pragma unroll 8
    for (int j = 0; j < 128; ++j) acc += up[(size_t)j*DDIM];
    g_xpart[(b*8+p)*DDIM + d] = acc;
}

// ---------------------------------------------------------------------------
// K2: per (i, 8-batch group): s = x@W_i ; v = squash(s) ; w_v = W_i@v.
// grid (32 i, 4 bq), 256 threads. W slice [256][64] staged once in smem.
// MODE 0: x from mean partials. MODE 1: x = sum of NJC g_xp partials.
// MODE 2: like 1 but write final v to out.
// (identical to round-2 version except MODE 1/2 partial count)
// ---------------------------------------------------------------------------
template<int MODE>
__global__ void k_sv(const float* __restrict__ W, float* __restrict__ out){
    int i = blockIdx.x, bq = blockIdx.y;
    int t = threadIdx.x;
    extern __shared__ float Wt_s[];          // [256][66] floats (67.6 KB)
    __shared__ float2 xsD[8][DDIM];          // duplicated x pairs
    __shared__ float  sm[8][DCAP];
    __shared__ float  vs[8][DCAP];

    // zero g_sum slots for the upcoming k_bupd accumulation
    if (MODE != 2 && t < 8) g_sum[(bq*8+t)*NCAP + i] = 0.f;

    // stage W[:, i*64 : i*64+64] -> Wt[d][m], pad 66
    #pragma unroll 4
    for (int p = 0; p < 16; ++p){
        int idx = t + 256*p;                 // 4096 float4s
        int d = idx >> 4, m4 = idx & 15;
        float4 w4 = *(const float4*)(W + (size_t)d*2048 + i*64 + m4*4);
        float* wp = &Wt_s[d*66 + m4*4];
        wp[0]=w4.x; wp[1]=w4.y; wp[2]=w4.z; wp[3]=w4.w;
    }
    // stage x (duplicated pairs)
    #pragma unroll
    for (int p = 0; p < 8; ++p){
        int idx = t + 256*p;
        int bb = idx >> 8, d = idx & 255;
        float a;
        if (MODE == 0){
            a = 0.f;
            #pragma unroll
            for (int q = 0; q < 8; ++q) a += g_xpart[(((bq*8+bb)*8)+q)*DDIM + d];
            a *= (1.0f/1024.0f);
        } else {
            size_t bi = (((size_t)(bq*8+bb))*NCAP + i)*DDIM + d;
            a = 0.f;
            #pragma unroll
            for (int q = 0; q < NJC; ++q) a += g_xp[(size_t)q*BB*NCAP*DDIM + bi];
        }
        xsD[bb][d] = make_float2(a, a);
    }
    __syncthreads();

    // phase s: thread (mp = t&31 -> m pair, bb = t>>5)
    {
        int mp = t & 31, bb = t >> 5;
        u64 acc = 0ull;
        const u64* xrow = (const u64*)&xsD[bb][0];
        #pragma unroll 8
        for (int d = 0; d < DDIM; ++d){
            u64 w2 = *(const u64*)&Wt_s[d*66 + 2*mp];
            fma2(acc, w2, xrow[d]);
        }
        float2 sp = unpk(acc);
        sm[bb][2*mp] = sp.x; sm[bb][2*mp+1] = sp.y;
    }
    __syncthreads();

    // squash: warp w handles bb = w
    {
        int w = t >> 5, lane = t & 31;
        float s0 = sm[w][lane], s1 = sm[w][lane+32];
        float q = s0*s0 + s1*s1;
        #pragma unroll
        for (int o = 16; o; o >>= 1) q += __shfl_xor_sync(0xffffffffu, q, o);
        float r = rsqrtf(q + 1e-7f);
        if (MODE == 2){
            size_t ob = ((size_t)(bq*8+w)*NCAP + i)*DCAP;
            out[ob + lane]      = s0*r;
            out[ob + lane + 32] = s1*r;
            return;
        }
        vs[w][lane] = s0*r; vs[w][lane+32] = s1*r;
    }
    __syncthreads();

    // phase w_v: thread d = t
    {
        float wv[8] = {0,0,0,0,0,0,0,0};
        #pragma unroll 8
        for (int m = 0; m < DCAP; ++m){
            float wtv = Wt_s[t*66 + m];
            #pragma unroll
            for (int b8 = 0; b8 < 8; ++b8) wv[b8] = fmaf(wtv, vs[b8][m], wv[b8]);
        }
        #pragma unroll
        for (int b8 = 0; b8 < 8; ++b8)
            g_wv[(((size_t)(bq*8+b8))*NCAP + i)*DDIM + t] = wv[b8];
    }
}

// ---------------------------------------------------------------------------
// K3: b[b,i,j] (+)= sum_d u[b,j,d]*wv[b,i,d]; epilogue: atomic sum of exp(b).
// grid (32 b, 4 jc), 256 threads. f32x2: j-pairs x i. Tile 256j x 32i.
// (identical to round-2 version — best measured composition)
// ---------------------------------------------------------------------------
template<bool ACC>
__global__ void k_bupd(const float* __restrict__ u){
    int b = blockIdx.x, jb = blockIdx.y*256;
    int t = threadIdx.x;
    extern __shared__ float2 wvD_s[];        // [256][33] float2 (67.6 KB)
    __shared__ float As[16][256];
    __shared__ float red[8][32];

    // stage wv duplicated: wvD[d][i] = {w,w}
    #pragma unroll 8
    for (int p = 0; p < 32; ++p){
        int idx = t + 256*p;                 // 8192
        int i = idx >> 8, d = idx & 255;
        float w = g_wv[((size_t)b*NCAP + i)*DDIM + d];
        wvD_s[d*33 + i] = make_float2(w, w);
    }

    int ti = t & 7, tj = t >> 3;
    u64 acc[4][4];
    #pragma unroll
    for (int q = 0; q < 4; ++q)
        #pragma unroll
        for (int k = 0; k < 4; ++k) acc[q][k] = 0ull;

    const float* ub = u + ((size_t)b*NN + jb + t)*DDIM;
    for (int dt = 0; dt < DDIM; dt += 16){
        __syncthreads();
        float4 v0 = *(const float4*)(ub + dt);
        float4 v1 = *(const float4*)(ub + dt + 4);
        float4 v2 = *(const float4*)(ub + dt + 8);
        float4 v3 = *(const float4*)(ub + dt + 12);
        As[ 0][t]=v0.x; As[ 1][t]=v0.y; As[ 2][t]=v0.z; As[ 3][t]=v0.w;
        As[ 4][t]=v1.x; As[ 5][t]=v1.y; As[ 6][t]=v1.z; As[ 7][t]=v1.w;
        As[ 8][t]=v2.x; As[ 9][t]=v2.y; As[10][t]=v2.z; As[11][t]=v2.w;
        As[12][t]=v3.x; As[13][t]=v3.y; As[14][t]=v3.z; As[15][t]=v3.w;
        __syncthreads();
        #pragma unroll
        for (int dd = 0; dd < 16; ++dd){
            u64 a0 = *(const u64*)&As[dd][tj*8 + 0];
            u64 a1 = *(const u64*)&As[dd][tj*8 + 2];
            u64 a2 = *(const u64*)&As[dd][tj*8 + 4];
            u64 a3 = *(const u64*)&As[dd][tj*8 + 6];
            const float2* wr = &wvD_s[(dt+dd)*33];
            u64 w0 = *(const u64*)&wr[ti];
            u64 w1 = *(const u64*)&wr[ti+8];
            u64 w2 = *(const u64*)&wr[ti+16];
            u64 w3 = *(const u64*)&wr[ti+24];
            fma2(acc[0][0], a0, w0); fma2(acc[1][0], a1, w0);
            fma2(acc[2][0], a2, w0); fma2(acc[3][0], a3, w0);
            fma2(acc[0][1], a0, w1); fma2(acc[1][1], a1, w1);
            fma2(acc[2][1], a2, w1); fma2(acc[3][1], a3, w1);
            fma2(acc[0][2], a0, w2); fma2(acc[1][2], a1, w2);
            fma2(acc[2][2], a2, w2); fma2(acc[3][2], a3, w2);
            fma2(acc[0][3], a0, w3); fma2(acc[1][3], a1, w3);
            fma2(acc[2][3], a2, w3); fma2(acc[3][3], a3, w3);
        }
    }

    // epilogue: store b (+= if ACC), accumulate exp sums per i
    float es[4];
    #pragma unroll
    for (int k = 0; k < 4; ++k){
        int i = ti + 8*k;
        float2 p0 = unpk(acc[0][k]), p1 = unpk(acc[1][k]);
        float2 p2 = unpk(acc[2][k]), p3 = unpk(acc[3][k]);
        float4 q0 = make_float4(p0.x, p0.y, p1.x, p1.y);
        float4 q1 = make_float4(p2.x, p2.y, p3.x, p3.y);
        float4* bp = (float4*)(g_b + ((size_t)b*NCAP + i)*NN + jb + tj*8);
        if (ACC){
            float4 o0 = bp[0], o1 = bp[1];
            q0.x+=o0.x; q0.y+=o0.y; q0.z+=o0.z; q0.w+=o0.w;
            q1.x+=o1.x; q1.y+=o1.y; q1.z+=o1.z; q1.w+=o1.w;
        }
        bp[0] = q0; bp[1] = q1;
        es[k] = __expf(q0.x)+__expf(q0.y)+__expf(q0.z)+__expf(q0.w)
              + __expf(q1.x)+__expf(q1.y)+__expf(q1.z)+__expf(q1.w);
    }
    #pragma unroll
    for (int k = 0; k < 4; ++k){
        es[k] += __shfl_down_sync(0xffffffffu, es[k], 16);
        es[k] += __shfl_down_sync(0xffffffffu, es[k], 8);
    }
    int w = t >> 5, lane = t & 31;
    if (lane < 8){
        #pragma unroll
        for (int k = 0; k < 4; ++k) red[w][k*8 + lane] = es[k];
    }
    __syncthreads();
    if (t < 32){
        float s = 0.f;
        #pragma unroll
        for (int ww = 0; ww < 8; ++ww) s += red[ww][t];
        atomicAdd(&g_sum[b*NCAP + t], s);     // i == t
    }
}

// ---------------------------------------------------------------------------
// K4: x partial: g_xp[jc][b,i,dslice] = sum_{j in chunk} c_ij * u[j,d].
// grid (32 b, 2 dh, 8 jc), 128 thr. Thread tile: 4 d-pairs x 4 i.
// (identical to round-3 version — measured 33.4 us)
// ---------------------------------------------------------------------------
__global__ void k_x(const float* __restrict__ u){
    int b = blockIdx.x, dh = blockIdx.y, jc = blockIdx.z;
    int t = threadIdx.x;
    int ig = t & 7, dg = t >> 3;                 // ig 0..7 (4 i each), dg 0..15 (4 pairs)
    __shared__ float  Us[32][132];               // [j][128 d]
    __shared__ float2 CsD[32][34];               // [j][32 i] duplicated
    __shared__ float  inv[NCAP];
    if (t < 32) inv[t] = 1.0f / g_sum[b*NCAP + t];

    u64 acc[4][4];
    #pragma unroll
    for (int p = 0; p < 4; ++p)
        #pragma unroll
        for (int q = 0; q < 4; ++q) acc[p][q] = 0ull;

    int j0 = jc*128;
    for (int jt = 0; jt < 128; jt += 32){
        __syncthreads();
        // stage Us (32j x 128d = 1024 float4)
        #pragma unroll
        for (int p = 0; p < 8; ++p){
            int lin = t + 128*p;
            int j = lin >> 5, f4 = lin & 31;
            float4 v4 = *(const float4*)(u + ((size_t)b*NN + j0 + jt + j)*DDIM + dh*128 + f4*4);
            *(float4*)&Us[j][f4*4] = v4;
        }
        // stage c (32j x 32i scalars)
        #pragma unroll
        for (int p = 0; p < 8; ++p){
            int lin = t + 128*p;
            int i = lin >> 5, jj = lin & 31;
            float bv = g_b[((size_t)b*NCAP + i)*NN + j0 + jt + jj];
            float c = __expf(bv) * inv[i];
            CsD[jj][i] = make_float2(c, c);
        }
        __syncthreads();
        #pragma unroll
        for (int jj = 0; jj < 32; ++jj){
            ulonglong2 A0 = *(const ulonglong2*)&Us[jj][dg*8];
            ulonglong2 A1 = *(const ulonglong2*)&Us[jj][dg*8 + 4];
            ulonglong2 C0 = *(const ulonglong2*)&CsD[jj][ig*4];
            ulonglong2 C1 = *(const ulonglong2*)&CsD[jj][ig*4 + 2];
            u64 a[4] = {A0.x, A0.y, A1.x, A1.y};
            u64 c[4] = {C0.x, C0.y, C1.x, C1.y};
            #pragma unroll
            for (int p = 0; p < 4; ++p)
                #pragma unroll
                for (int q = 0; q < 4; ++q)
                    fma2(acc[p][q], a[p], c[q]);
        }
    }
    // write partials
    #pragma unroll
    for (int q = 0; q < 4; ++q){
        int i = ig*4 + q;
        float2 r0 = unpk(acc[0][q]), r1 = unpk(acc[1][q]);
        float2 r2 = unpk(acc[2][q]), r3 = unpk(acc[3][q]);
        float* xp = g_xp + (size_t)jc*BB*NCAP*DDIM
                  + ((size_t)b*NCAP + i)*DDIM + dh*128 + dg*8;
        *(float4*)xp       = make_float4(r0.x, r0.y, r1.x, r1.y);
        *(float4*)(xp + 4) = make_float4(r2.x, r2.y, r3.x, r3.y);
    }
}

// ---------------------------------------------------------------------------
extern "C" void kernel_launch(void* const* d_in, const int* in_sizes, int n_in,
                              void* d_out, int out_size){
    const float* u = (const float*)d_in[0];
    const float* W = (const float*)d_in[1];
    if (n_in >= 2 && in_sizes[0] < in_sizes[1]){
        u = (const float*)d_in[1];
        W = (const float*)d_in[0];
    }
    float* out = (float*)d_out;

    const int SV_SMEM  = 256*66*sizeof(float);    // 67584
    const int BUP_SMEM = 256*33*sizeof(float2);   // 67584
    static bool attr_done = false;
    if (!attr_done){
        cudaFuncSetAttribute(k_sv<0>,       cudaFuncAttributeMaxDynamicSharedMemorySize, SV_SMEM);
        cudaFuncSetAttribute(k_sv<1>,       cudaFuncAttributeMaxDynamicSharedMemorySize, SV_SMEM);
        cudaFuncSetAttribute(k_sv<2>,       cudaFuncAttributeMaxDynamicSharedMemorySize, SV_SMEM);
        cudaFuncSetAttribute(k_bupd<false>, cudaFuncAttributeMaxDynamicSharedMemorySize, BUP_SMEM);
        cudaFuncSetAttribute(k_bupd<true>,  cudaFuncAttributeMaxDynamicSharedMemorySize, BUP_SMEM);
        attr_done = true;
    }

    // iter 0 (softmax of zeros == mean)
    k_meanpart   <<<dim3(32,8),   256>>>(u);
    k_sv<0>      <<<dim3(32,4),   256, SV_SMEM>>>(W, out);
    k_bupd<false><<<dim3(32,4),   256, BUP_SMEM>>>(u);
    // iter 1
    k_x          <<<dim3(32,2,8), 128>>>(u);
    k_sv<1>      <<<dim3(32,4),   256, SV_SMEM>>>(W, out);
    k_bupd<true> <<<dim3(32,4),   256, BUP_SMEM>>>(u);
    // iter 2 (final)
    k_x          <<<dim3(32,2,8), 128>>>(u);
    k_sv<2>      <<<dim3(32,4),   256, SV_SMEM>>>(W, out);
}